// round 6
// baseline (speedup 1.0000x reference)
#include <cuda_runtime.h>

// Shapes (fixed): x (1,384,256), gamma/beta (256), Wa/Wb (32,256),
// Wo (128,1024), bo (128) -> z (1,384,384,128) fp32
//
//   kA: layernorm(x) -> a = xn.Wa^T, b = xn.Wb^T          (384x32 each)
//   kB: U[i][o][d] = sum_c a[i][c] * Wo[o*1024 + c*32 + d] (384x128x32)
//   kC: z[i][j][o] = bo[o] + sum_d U[i][o][d] * b[j][d]
//
// kB/kC inner products use packed fma.rn.f32x2. Operands are loaded from
// shared memory as ulonglong2 (LDS.128 -> two packed 64-bit regs) so there
// are NO pack movs in the hot loops.

#define L   384
#define DIM 256
#define H   32
#define OUT 128

typedef unsigned long long u64;

__device__ __forceinline__ u64 ffma2(u64 a, u64 b, u64 c) {
    u64 d;
    asm("fma.rn.f32x2 %0, %1, %2, %3;" : "=l"(d) : "l"(a), "l"(b), "l"(c));
    return d;
}
__device__ __forceinline__ u64 pack2(float lo, float hi) {
    u64 d;
    asm("mov.b64 %0, {%1, %2};" : "=l"(d) : "f"(lo), "f"(hi));
    return d;
}
__device__ __forceinline__ float2 unpack2(u64 v) {
    float2 r;
    asm("mov.b64 {%0, %1}, %2;" : "=f"(r.x), "=f"(r.y) : "l"(v));
    return r;
}

__device__ float g_U[L * OUT * H];   // 6.29 MB scratch, [i][o][d]
__device__ float g_a[L * H];         // [l][h]
__device__ float g_b[L * H];         // [l][h]

// ---------------------------------------------------------------------------
// Kernel A: layernorm + two 256-dot GEMVs per row. 384 blocks x 256 threads.
// (Round-0 structure: warp-coalesced scalar W reads, warp reductions.)
// ---------------------------------------------------------------------------
__global__ void __launch_bounds__(256) kA(
    const float* __restrict__ x, const float* __restrict__ gamma,
    const float* __restrict__ beta, const float* __restrict__ Wa,
    const float* __restrict__ Wb)
{
    const int l = blockIdx.x;
    const int t = threadIdx.x;
    const int lane = t & 31, w = t >> 5;

    __shared__ float xn_sh[DIM];
    __shared__ float red[16];
    __shared__ float mu_s, rstd_s;

    float v = x[l * DIM + t];

    float s = v, s2 = v * v;
    #pragma unroll
    for (int off = 16; off; off >>= 1) {
        s  += __shfl_down_sync(0xffffffffu, s,  off);
        s2 += __shfl_down_sync(0xffffffffu, s2, off);
    }
    if (lane == 0) { red[w] = s; red[8 + w] = s2; }
    __syncthreads();
    if (t == 0) {
        float S = 0.f, S2 = 0.f;
        #pragma unroll
        for (int k = 0; k < 8; k++) { S += red[k]; S2 += red[8 + k]; }
        float mu  = S * (1.0f / DIM);
        float var = S2 * (1.0f / DIM) - mu * mu;
        mu_s   = mu;
        rstd_s = rsqrtf(var + 1e-5f);
    }
    __syncthreads();

    xn_sh[t] = (v - mu_s) * rstd_s * gamma[t] + beta[t];
    __syncthreads();

    // 64 dot products of length 256: warp w handles outputs w*8 .. w*8+7
    #pragma unroll
    for (int q = 0; q < 8; q++) {
        int idx = w * 8 + q;                 // 0..63: 0..31 -> a, 32..63 -> b
        int h = idx & 31;
        const float* Wrow = (idx < 32 ? Wa : Wb) + h * DIM;
        float acc = 0.f;
        #pragma unroll
        for (int k = 0; k < 8; k++)
            acc += xn_sh[k * 32 + lane] * Wrow[k * 32 + lane];
        #pragma unroll
        for (int off = 16; off; off >>= 1)
            acc += __shfl_xor_sync(0xffffffffu, acc, off);
        if (lane == 0) {
            float* outp = (idx < 32) ? g_a : g_b;
            outp[l * H + h] = acc;
        }
    }
}

// ---------------------------------------------------------------------------
// Kernel B: U[i][o][d] = sum_c a[i][c] * Wo[o*1024 + c*32 + d]
// grid (48, 4): 8 i's per block, 32 o's per block. lane = d (coalesced).
// a transposed in smem ([c][i]); i-pairs read as ulonglong2 (pre-packed).
// ---------------------------------------------------------------------------
__global__ void __launch_bounds__(256) kB(const float* __restrict__ Wo)
{
    const int it0 = blockIdx.x * 8;
    const int oc  = blockIdx.y;
    const int t = threadIdx.x;
    const int lane = t & 31, w = t >> 5;

    __shared__ __align__(16) float a_sh[H * 8];   // [c][i]
    {
        int i = t >> 5, c = t & 31;
        a_sh[c * 8 + i] = g_a[(it0 + i) * H + c];
    }
    __syncthreads();

    #pragma unroll
    for (int p = 0; p < 4; p++) {
        const int o = oc * 32 + p * 8 + w;
        const float* wrow = Wo + o * (H * H) + lane;
        u64 acc2[4] = {0ull, 0ull, 0ull, 0ull};
        #pragma unroll
        for (int c = 0; c < H; c++) {
            float wv = wrow[c * H];
            u64 wv2 = pack2(wv, wv);
            ulonglong2 p0 = *(const ulonglong2*)&a_sh[c * 8];
            ulonglong2 p1 = *(const ulonglong2*)&a_sh[c * 8 + 4];
            acc2[0] = ffma2(p0.x, wv2, acc2[0]);
            acc2[1] = ffma2(p0.y, wv2, acc2[1]);
            acc2[2] = ffma2(p1.x, wv2, acc2[2]);
            acc2[3] = ffma2(p1.y, wv2, acc2[3]);
        }
        #pragma unroll
        for (int ii = 0; ii < 4; ii++) {
            float2 r = unpack2(acc2[ii]);
            g_U[((it0 + 2 * ii)     * OUT + o) * H + lane] = r.x;
            g_U[((it0 + 2 * ii + 1) * OUT + o) * H + lane] = r.y;
        }
    }
}

// ---------------------------------------------------------------------------
// Kernel C: z[i][j][o] = bo[o] + sum_d U[i][o][d] * b[j][d]
// grid (384, 6): one i, 64 j's per block. 256 threads = 8 warps.
// Thread: lane -> 4 o's (o = lane + 32*oo), warp -> 8 j's. 32 outputs/thread.
// All smem operands loaded as ulonglong2 -> zero pack movs in hot loop.
// U row stride 36 floats (144 B): 16B-aligned, conflict-free in 4 phases.
// ---------------------------------------------------------------------------
#define USTRIDE 36
__global__ void __launch_bounds__(256) kC(
    const float* __restrict__ bo, float* __restrict__ z)
{
    const int i  = blockIdx.x;
    const int jt = blockIdx.y;
    const int t = threadIdx.x;
    const int lane = t & 31, w = t >> 5;

    __shared__ __align__(16) float U_sh[OUT * USTRIDE];  // 18432 B
    __shared__ __align__(16) float b_sh[64 * H];         // 8192 B

    // Load U[i] : 4096 floats = 1024 float4, pad-stride store
    {
        const float4* Ug4 = (const float4*)(g_U + i * (OUT * H));
        #pragma unroll
        for (int it = 0; it < 4; it++) {
            int idx = t + it * 256;
            int o = idx >> 3, d4 = idx & 7;
            float4 vv = Ug4[idx];
            *((float4*)&U_sh[o * USTRIDE + d4 * 4]) = vv;
        }
    }
    // Load b tile: 2048 floats = 512 float4
    {
        const float4* bg4 = (const float4*)(g_b + jt * 64 * H);
        #pragma unroll
        for (int it = 0; it < 2; it++) {
            int idx = t + it * 256;
            ((float4*)b_sh)[idx] = bg4[idx];
        }
    }
    __syncthreads();

    const int j0 = w * 8;

    u64 acc2[8][4];
    #pragma unroll
    for (int jj = 0; jj < 8; jj++)
        #pragma unroll
        for (int oo = 0; oo < 4; oo++) acc2[jj][oo] = 0ull;

    #pragma unroll 1
    for (int dc = 0; dc < H; dc += 8) {
        u64 u2[4][4];
        #pragma unroll
        for (int oo = 0; oo < 4; oo++) {
            const float* up = &U_sh[(lane + 32 * oo) * USTRIDE + dc];
            ulonglong2 v0 = *(const ulonglong2*)(up);
            ulonglong2 v1 = *(const ulonglong2*)(up + 4);
            u2[oo][0] = v0.x; u2[oo][1] = v0.y;
            u2[oo][2] = v1.x; u2[oo][3] = v1.y;
        }
        #pragma unroll
        for (int jj = 0; jj < 8; jj++) {
            const float* bp = &b_sh[(j0 + jj) * H + dc];
            ulonglong2 w0 = *(const ulonglong2*)(bp);
            ulonglong2 w1 = *(const ulonglong2*)(bp + 4);
            u64 b20 = w0.x, b21 = w0.y, b22 = w1.x, b23 = w1.y;
            #pragma unroll
            for (int oo = 0; oo < 4; oo++) {
                acc2[jj][oo] = ffma2(u2[oo][0], b20, acc2[jj][oo]);
                acc2[jj][oo] = ffma2(u2[oo][1], b21, acc2[jj][oo]);
                acc2[jj][oo] = ffma2(u2[oo][2], b22, acc2[jj][oo]);
                acc2[jj][oo] = ffma2(u2[oo][3], b23, acc2[jj][oo]);
            }
        }
    }

    float bov[4];
    #pragma unroll
    for (int oo = 0; oo < 4; oo++) bov[oo] = bo[lane + 32 * oo];

    long base = ((long)(i * L + jt * 64 + j0)) * OUT;
    #pragma unroll
    for (int jj = 0; jj < 8; jj++) {
        float* zp = z + base + (long)jj * OUT + lane;
        #pragma unroll
        for (int oo = 0; oo < 4; oo++) {
            float2 r = unpack2(acc2[jj][oo]);
            zp[32 * oo] = (r.x + r.y) + bov[oo];
        }
    }
}

// ---------------------------------------------------------------------------
extern "C" void kernel_launch(void* const* d_in, const int* in_sizes, int n_in,
                              void* d_out, int out_size)
{
    const float* x     = (const float*)d_in[0];
    const float* gamma = (const float*)d_in[1];
    const float* beta  = (const float*)d_in[2];
    const float* Wa    = (const float*)d_in[3];
    const float* Wb    = (const float*)d_in[4];
    const float* Wo    = (const float*)d_in[5];
    const float* bo    = (const float*)d_in[6];
    float* z = (float*)d_out;

    kA<<<L, 256>>>(x, gamma, beta, Wa, Wb);
    kB<<<dim3(48, 4), 256>>>(Wo);
    kC<<<dim3(L, 6), 256>>>(bo, z);
}

// round 7
// speedup vs baseline: 1.2550x; 1.2550x over previous
#include <cuda_runtime.h>
#include <cstdint>

// Shapes (fixed): x (1,384,256), gamma/beta (256), Wa/Wb (32,256),
// Wo (128,1024), bo (128) -> z (1,384,384,128) fp32
//
//   kA: layernorm(x) -> a = xn.Wa^T, b = xn.Wb^T          (384x32 each)
//   kB: U[i][o][d] = sum_c a[i][c] * Wo[o*1024 + c*32 + d] (384x128x32)
//   kC: z[i][j][o] = bo[o] + sum_d U[i][o][d] * b[j][d]
//       -> per i a (384 x 32) @ (32 x 128) GEMM via mma.sync.m16n8k8.tf32
//          with 3xTF32 split (hi*hi + lo*hi + hi*lo) for fp32-grade accuracy.

#define L   384
#define DIM 256
#define H   32
#define OUT 128

__device__ float g_U[L * OUT * H];   // 6.29 MB scratch, [i][o][d]
__device__ float g_a[L * H];         // [l][h]
__device__ float g_b[L * H];         // [l][h]

__device__ __forceinline__ uint32_t f2tf32(float x) {
    uint32_t r;
    asm("cvt.rna.tf32.f32 %0, %1;" : "=r"(r) : "f"(x));
    return r;
}
// hi/lo split: hi = tf32(x), lo = tf32(x - hi)
__device__ __forceinline__ uint2 tf32_split(float x) {
    uint2 r;
    r.x = f2tf32(x);
    r.y = f2tf32(x - __uint_as_float(r.x));
    return r;
}

#define MMA_TF32(c, a0, a1, a2, a3, b0, b1)                                   \
    asm volatile(                                                             \
        "mma.sync.aligned.m16n8k8.row.col.f32.tf32.tf32.f32 "                 \
        "{%0,%1,%2,%3}, {%4,%5,%6,%7}, {%8,%9}, {%0,%1,%2,%3};\n"             \
        : "+f"((c)[0]), "+f"((c)[1]), "+f"((c)[2]), "+f"((c)[3])              \
        : "r"(a0), "r"(a1), "r"(a2), "r"(a3), "r"(b0), "r"(b1))

// ---------------------------------------------------------------------------
// Kernel A: layernorm + two 256-dot GEMVs per row. 384 blocks x 256 threads.
// GEMV: warp owns 8 consecutive rows of one weight matrix; k-loop outer so
// the 8 FMA chains are independent (ILP), reductions pipelined at the end.
// W reads stay fully coalesced (Wrow[k*32+lane]).
// ---------------------------------------------------------------------------
__global__ void __launch_bounds__(256) kA(
    const float* __restrict__ x, const float* __restrict__ gamma,
    const float* __restrict__ beta, const float* __restrict__ Wa,
    const float* __restrict__ Wb)
{
    const int l = blockIdx.x;
    const int t = threadIdx.x;
    const int lane = t & 31, w = t >> 5;

    __shared__ float xn_sh[DIM];
    __shared__ float red[16];
    __shared__ float mu_s, rstd_s;

    float v = x[l * DIM + t];

    float s = v, s2 = v * v;
    #pragma unroll
    for (int off = 16; off; off >>= 1) {
        s  += __shfl_down_sync(0xffffffffu, s,  off);
        s2 += __shfl_down_sync(0xffffffffu, s2, off);
    }
    if (lane == 0) { red[w] = s; red[8 + w] = s2; }
    __syncthreads();
    if (t == 0) {
        float S = 0.f, S2 = 0.f;
        #pragma unroll
        for (int k = 0; k < 8; k++) { S += red[k]; S2 += red[8 + k]; }
        float mu  = S * (1.0f / DIM);
        float var = S2 * (1.0f / DIM) - mu * mu;
        mu_s   = mu;
        rstd_s = rsqrtf(var + 1e-5f);
    }
    __syncthreads();

    xn_sh[t] = (v - mu_s) * rstd_s * gamma[t] + beta[t];
    __syncthreads();

    // warps 0..3 -> Wa rows h0..h0+7; warps 4..7 -> Wb rows h0..h0+7
    const int h0 = (w & 3) * 8;
    const float* M = ((w < 4) ? Wa : Wb) + h0 * DIM + lane;

    float accq[8];
    #pragma unroll
    for (int q = 0; q < 8; q++) accq[q] = 0.f;

    #pragma unroll
    for (int k = 0; k < 8; k++) {
        float xv = xn_sh[k * 32 + lane];
        #pragma unroll
        for (int q = 0; q < 8; q++)
            accq[q] += xv * M[q * DIM + k * 32];
    }

    float* outp = (w < 4) ? g_a : g_b;
    #pragma unroll
    for (int q = 0; q < 8; q++) {
        float a = accq[q];
        #pragma unroll
        for (int off = 16; off; off >>= 1)
            a += __shfl_xor_sync(0xffffffffu, a, off);
        if (lane == 0) outp[l * H + h0 + q] = a;
    }
}

// ---------------------------------------------------------------------------
// Kernel B: U[i][o][d] = sum_c a[i][c] * Wo[o*1024 + c*32 + d]
// grid (48, 4): 8 i's per block, 32 o's per block (round-0 scalar form).
// ---------------------------------------------------------------------------
__global__ void __launch_bounds__(256) kB(const float* __restrict__ Wo)
{
    const int it0 = blockIdx.x * 8;
    const int oc  = blockIdx.y;
    const int t = threadIdx.x;
    const int lane = t & 31, w = t >> 5;

    __shared__ float a_sh[8 * H];
    a_sh[t] = g_a[it0 * H + t];
    __syncthreads();

    #pragma unroll
    for (int p = 0; p < 4; p++) {
        const int o = oc * 32 + p * 8 + w;
        const float* wrow = Wo + o * (H * H) + lane;
        float acc[8];
        #pragma unroll
        for (int i = 0; i < 8; i++) acc[i] = 0.f;
        #pragma unroll
        for (int c = 0; c < H; c++) {
            float wv = wrow[c * H];
            #pragma unroll
            for (int i = 0; i < 8; i++)
                acc[i] += a_sh[i * H + c] * wv;
        }
        #pragma unroll
        for (int i = 0; i < 8; i++)
            g_U[((it0 + i) * OUT + o) * H + lane] = acc[i];
    }
}

// ---------------------------------------------------------------------------
// Kernel C: per-i GEMM Z_i[j,o] = bo[o] + B[j,:].U_i[o,:]^T via tf32 MMA.
// grid (384, 3): one i, 128 j's per block. 256 threads = 8 warps.
// Warp w owns j-tile [w*16, w*16+16); loops 16 o-tiles of 8.
// smem: hi/lo tf32 pairs (uint2), row stride 36 uint2 = 288 B
// (conflict-free: per LDS.64 phase bank = (8g+2t) % 32, all distinct).
// 3 MMAs per (otile, kstep): hi*hi + lo*hi + hi*lo.
// ---------------------------------------------------------------------------
#define KC_RS 36                      // row stride in uint2
#define KC_SMEM (2 * 128 * KC_RS * 8) // 73728 bytes

__global__ void __launch_bounds__(256) kC(
    const float* __restrict__ bo, float* __restrict__ z)
{
    extern __shared__ uint2 dsm[];
    uint2* Ub = dsm;                  // [o][d]  128 x 36
    uint2* Bs = dsm + 128 * KC_RS;    // [j_local][d]  128 x 36

    const int i     = blockIdx.x;
    const int jbase = blockIdx.y * 128;
    const int t = threadIdx.x;
    const int lane = t & 31, w = t >> 5;
    const int g = lane >> 2, t4 = lane & 3;

    // Load U_i (128x32 f32) -> split tf32 hi/lo pairs
    {
        const float4* Ug4 = (const float4*)(g_U + (size_t)i * OUT * H);
        #pragma unroll
        for (int it = 0; it < 4; it++) {
            int idx = t + it * 256;           // float4 index, 1024 total
            int o = idx >> 3, dq = idx & 7;
            float4 v = Ug4[idx];
            uint2* dst = Ub + o * KC_RS + dq * 4;
            dst[0] = tf32_split(v.x);
            dst[1] = tf32_split(v.y);
            dst[2] = tf32_split(v.z);
            dst[3] = tf32_split(v.w);
        }
    }
    // Load b tile (128x32 f32) -> split tf32
    {
        const float4* bg4 = (const float4*)(g_b + (size_t)jbase * H);
        #pragma unroll
        for (int it = 0; it < 4; it++) {
            int idx = t + it * 256;
            int j = idx >> 3, dq = idx & 7;
            float4 v = bg4[idx];
            uint2* dst = Bs + j * KC_RS + dq * 4;
            dst[0] = tf32_split(v.x);
            dst[1] = tf32_split(v.y);
            dst[2] = tf32_split(v.z);
            dst[3] = tf32_split(v.w);
        }
    }
    __syncthreads();

    float acc[16][4];
    #pragma unroll
    for (int ot = 0; ot < 16; ot++)
        #pragma unroll
        for (int c = 0; c < 4; c++) acc[ot][c] = 0.f;

    const uint2* aptr = Bs + (w * 16 + g) * KC_RS + t4;
    const uint2* bbase = Ub + g * KC_RS + t4;

    #pragma unroll
    for (int kk = 0; kk < 4; kk++) {
        // A fragment: rows (g, g+8) of this warp's j-tile, cols t4, t4+4
        const uint2* ap = aptr + kk * 8;
        uint2 A0 = ap[0];
        uint2 A2 = ap[4];
        uint2 A1 = ap[8 * KC_RS];
        uint2 A3 = ap[8 * KC_RS + 4];

        const uint2* bp0 = bbase + kk * 8;
        #pragma unroll
        for (int ot = 0; ot < 16; ot++) {
            const uint2* bp = bp0 + ot * 8 * KC_RS;
            uint2 B0 = bp[0];
            uint2 B1 = bp[4];
            MMA_TF32(acc[ot], A0.x, A1.x, A2.x, A3.x, B0.x, B1.x); // hi*hi
            MMA_TF32(acc[ot], A0.y, A1.y, A2.y, A3.y, B0.x, B1.x); // lo*hi
            MMA_TF32(acc[ot], A0.x, A1.x, A2.x, A3.x, B0.y, B1.y); // hi*lo
        }
    }

    // Store: c0,c1 -> row g, cols 2*t4, 2*t4+1; c2,c3 -> row g+8
    const float2* bo2 = (const float2*)bo;
    size_t zrow = ((size_t)i * L + jbase + w * 16 + g) * OUT;
    #pragma unroll
    for (int ot = 0; ot < 16; ot++) {
        int o = ot * 8 + 2 * t4;
        float2 bb = bo2[o >> 1];
        float2 v0 = make_float2(acc[ot][0] + bb.x, acc[ot][1] + bb.y);
        float2 v1 = make_float2(acc[ot][2] + bb.x, acc[ot][3] + bb.y);
        *(float2*)(z + zrow + o)           = v0;
        *(float2*)(z + zrow + 8 * OUT + o) = v1;
    }
}

// ---------------------------------------------------------------------------
extern "C" void kernel_launch(void* const* d_in, const int* in_sizes, int n_in,
                              void* d_out, int out_size)
{
    const float* x     = (const float*)d_in[0];
    const float* gamma = (const float*)d_in[1];
    const float* beta  = (const float*)d_in[2];
    const float* Wa    = (const float*)d_in[3];
    const float* Wb    = (const float*)d_in[4];
    const float* Wo    = (const float*)d_in[5];
    const float* bo    = (const float*)d_in[6];
    float* z = (float*)d_out;

    cudaFuncSetAttribute(kC, cudaFuncAttributeMaxDynamicSharedMemorySize,
                         KC_SMEM);

    kA<<<L, 256>>>(x, gamma, beta, Wa, Wb);
    kB<<<dim3(48, 4), 256>>>(Wo);
    kC<<<dim3(L, 3), 256, KC_SMEM>>>(bo, z);
}

// round 9
// speedup vs baseline: 1.3716x; 1.0929x over previous
#include <cuda_runtime.h>
#include <cuda_bf16.h>
#include <cstdint>

// Shapes (fixed): x (1,384,256), gamma/beta (256), Wa/Wb (32,256),
// Wo (128,1024), bo (128) -> z (1,384,384,128) fp32
//
//   kA: layernorm(x) -> a = xn.Wa^T (fp32), b = xn.Wb^T (split-bf16)
//   kB: U[i][o][d] = sum_c a[i][c]*Wo[o*1024+c*32+d], stored split-bf16
//   kC: z[i][j][o] = bo[o] + sum_d U[i][o][d]*b[j][d]
//       per-i (384x32)@(32x128) GEMM via mma.sync.m16n8k16.bf16 with
//       3-term split (hi*hi + lo*hi + hi*lo); fp32 accumulation.
//
// Split storage format: uint2 per d-pair = {bf16x2(hi_d, hi_d1), bf16x2(lo...)}.

#define L   384
#define DIM 256
#define H   32
#define OUT 128

__device__ float g_a[L * H];             // fp32 [l][h] (kB input)
__device__ uint2 g_b2[L * 16];           // split-bf16 b, 16 d-pairs per row
__device__ uint2 g_U2[L * OUT * 16];     // split-bf16 U, [i][o][dpair]

// split (x,y) fp32 pair -> {hi bf16x2, lo bf16x2}
__device__ __forceinline__ uint2 split2(float x, float y) {
    __nv_bfloat162 h = __floats2bfloat162_rn(x, y);
    float2 hf = __bfloat1622float2(h);
    __nv_bfloat162 lo = __floats2bfloat162_rn(x - hf.x, y - hf.y);
    uint2 r;
    r.x = *reinterpret_cast<unsigned*>(&h);
    r.y = *reinterpret_cast<unsigned*>(&lo);
    return r;
}

#define MMA_BF16(c, a0, a1, a2, a3, b0, b1)                                   \
    asm volatile(                                                             \
        "mma.sync.aligned.m16n8k16.row.col.f32.bf16.bf16.f32 "                \
        "{%0,%1,%2,%3}, {%4,%5,%6,%7}, {%8,%9}, {%0,%1,%2,%3};\n"             \
        : "+f"((c)[0]), "+f"((c)[1]), "+f"((c)[2]), "+f"((c)[3])              \
        : "r"(a0), "r"(a1), "r"(a2), "r"(a3), "r"(b0), "r"(b1))

// ---------------------------------------------------------------------------
// Kernel A: layernorm + two 256-dot GEMVs per row. 384 blocks x 256 threads.
// ---------------------------------------------------------------------------
__global__ void __launch_bounds__(256) kA(
    const float* __restrict__ x, const float* __restrict__ gamma,
    const float* __restrict__ beta, const float* __restrict__ Wa,
    const float* __restrict__ Wb)
{
    const int l = blockIdx.x;
    const int t = threadIdx.x;
    const int lane = t & 31, w = t >> 5;

    __shared__ float xn_sh[DIM];
    __shared__ float red[16];
    __shared__ float mu_s, rstd_s;

    float v = x[l * DIM + t];

    float s = v, s2 = v * v;
    #pragma unroll
    for (int off = 16; off; off >>= 1) {
        s  += __shfl_down_sync(0xffffffffu, s,  off);
        s2 += __shfl_down_sync(0xffffffffu, s2, off);
    }
    if (lane == 0) { red[w] = s; red[8 + w] = s2; }
    __syncthreads();
    if (t == 0) {
        float S = 0.f, S2 = 0.f;
        #pragma unroll
        for (int k = 0; k < 8; k++) { S += red[k]; S2 += red[8 + k]; }
        float mu  = S * (1.0f / DIM);
        float var = S2 * (1.0f / DIM) - mu * mu;
        mu_s   = mu;
        rstd_s = rsqrtf(var + 1e-5f);
    }
    __syncthreads();

    xn_sh[t] = (v - mu_s) * rstd_s * gamma[t] + beta[t];
    __syncthreads();

    const int h0 = (w & 3) * 8;
    const float* M = ((w < 4) ? Wa : Wb) + h0 * DIM + lane;

    float accq[8];
    #pragma unroll
    for (int q = 0; q < 8; q++) accq[q] = 0.f;

    #pragma unroll
    for (int k = 0; k < 8; k++) {
        float xv = xn_sh[k * 32 + lane];
        #pragma unroll
        for (int q = 0; q < 8; q++)
            accq[q] += xv * M[q * DIM + k * 32];
    }

    // interleaved xor-reductions: 5 levels, 8 independent shfls per level
    #pragma unroll
    for (int off = 16; off; off >>= 1) {
        #pragma unroll
        for (int q = 0; q < 8; q++)
            accq[q] += __shfl_xor_sync(0xffffffffu, accq[q], off);
    }

    if (lane == 0) {
        if (w < 4) {
            #pragma unroll
            for (int q = 0; q < 8; q++)
                g_a[l * H + h0 + q] = accq[q];
        } else {
            #pragma unroll
            for (int p = 0; p < 4; p++)
                g_b2[l * 16 + (h0 >> 1) + p] = split2(accq[2*p], accq[2*p+1]);
        }
    }
}

// ---------------------------------------------------------------------------
// Kernel B: U[i][o][d] = sum_c a[i][c] * Wo[o*1024 + c*32 + d]
// grid (48, 8): 8 i's, 16 o's per block. lane = d (coalesced Wo reads).
// Output written in split-bf16 format (d-pairs via lane-neighbor shuffle).
// ---------------------------------------------------------------------------
__global__ void __launch_bounds__(256) kB(const float* __restrict__ Wo)
{
    const int it0 = blockIdx.x * 8;
    const int oc  = blockIdx.y;
    const int t = threadIdx.x;
    const int lane = t & 31, w = t >> 5;

    __shared__ float a_sh[8 * H];
    a_sh[t] = g_a[it0 * H + t];
    __syncthreads();

    #pragma unroll
    for (int p = 0; p < 2; p++) {
        const int o = oc * 16 + p * 8 + w;
        const float* wrow = Wo + o * (H * H) + lane;
        float acc[8];
        #pragma unroll
        for (int i = 0; i < 8; i++) acc[i] = 0.f;
        #pragma unroll
        for (int c = 0; c < H; c++) {
            float wv = wrow[c * H];
            #pragma unroll
            for (int i = 0; i < 8; i++)
                acc[i] += a_sh[i * H + c] * wv;
        }
        // form d-pairs: even lane holds (d, d+1)
        #pragma unroll
        for (int i = 0; i < 8; i++) {
            float other = __shfl_xor_sync(0xffffffffu, acc[i], 1);
            if ((lane & 1) == 0) {
                g_U2[((it0 + i) * OUT + o) * 16 + (lane >> 1)] =
                    split2(acc[i], other);
            }
        }
    }
}

// ---------------------------------------------------------------------------
// Kernel C: per-i GEMM Z_i[j,o] = bo[o] + B[j,:].U_i[o,:]^T, bf16 MMA.
// grid (384, 3): one i, 128 j per block, 256 threads = 8 warps.
// Warp w: j-tile [w*16, w*16+16); 16 o-tiles of 8; kk in {0,1} (k16 each).
// smem rows: 16 data uint2 + pad, stride 20 uint2 (160B). MMA operand LDS.64
// conflict-free (per 16-lane phase bank = (8g+2t4)%32, all distinct).
// 3 MMAs per (ot,kk): hi*hi + lo*hi + hi*lo.
// ---------------------------------------------------------------------------
#define RS 20   // row stride in uint2

__global__ void __launch_bounds__(256) kC(
    const float* __restrict__ bo, float* __restrict__ z)
{
    __shared__ uint2 Ub[OUT * RS];   // 20480 B
    __shared__ uint2 Bs[128 * RS];   // 20480 B

    const int i     = blockIdx.x;
    const int jbase = blockIdx.y * 128;
    const int t = threadIdx.x;
    const int lane = t & 31, w = t >> 5;
    const int g = lane >> 2, t4 = lane & 3;

    // Copy-in (no conversion): each matrix is 128 rows x 8 uint4 = 1024 uint4.
    {
        const uint4* Ug = (const uint4*)(g_U2 + (size_t)i * OUT * 16);
        const uint4* Bg = (const uint4*)(g_b2 + (size_t)jbase * 16);
        #pragma unroll
        for (int it = 0; it < 4; it++) {
            int idx = t + it * 256;          // 0..1023
            int row = idx >> 3, q = idx & 7; // 8 uint4 per row
            *(uint4*)(Ub + row * RS + q * 2) = Ug[idx];
            *(uint4*)(Bs + row * RS + q * 2) = Bg[idx];
        }
    }
    __syncthreads();

    float acc[16][4];
    #pragma unroll
    for (int ot = 0; ot < 16; ot++)
        #pragma unroll
        for (int c = 0; c < 4; c++) acc[ot][c] = 0.f;

    const int jr = w * 16;

    #pragma unroll
    for (int kk = 0; kk < 2; kk++) {
        // A fragment (B-tile rows j): rows jr+g, jr+g+8; d-pairs t4, t4+4
        const uint2* ap = Bs + (jr + g) * RS + kk * 8 + t4;
        uint2 A00 = ap[0];
        uint2 A01 = ap[4];
        uint2 A10 = ap[8 * RS];
        uint2 A11 = ap[8 * RS + 4];

        const uint2* bp0 = Ub + g * RS + kk * 8 + t4;
        #pragma unroll
        for (int ot = 0; ot < 16; ot++) {
            const uint2* bp = bp0 + ot * 8 * RS;
            uint2 B0 = bp[0];
            uint2 B1 = bp[4];
            MMA_BF16(acc[ot], A00.x, A10.x, A01.x, A11.x, B0.x, B1.x); // hh
            MMA_BF16(acc[ot], A00.y, A10.y, A01.y, A11.y, B0.x, B1.x); // lh
            MMA_BF16(acc[ot], A00.x, A10.x, A01.x, A11.x, B0.y, B1.y); // hl
        }
    }

    // Store: c0,c1 -> row g, cols 2t4,2t4+1; c2,c3 -> row g+8
    const float2* bo2 = (const float2*)bo;
    size_t zrow = ((size_t)i * L + jbase + jr + g) * OUT;
    #pragma unroll
    for (int ot = 0; ot < 16; ot++) {
        int o = ot * 8 + 2 * t4;
        float2 bb = bo2[o >> 1];
        float2 v0 = make_float2(acc[ot][0] + bb.x, acc[ot][1] + bb.y);
        float2 v1 = make_float2(acc[ot][2] + bb.x, acc[ot][3] + bb.y);
        *(float2*)(z + zrow + o)           = v0;
        *(float2*)(z + zrow + 8 * OUT + o) = v1;
    }
}

// ---------------------------------------------------------------------------
extern "C" void kernel_launch(void* const* d_in, const int* in_sizes, int n_in,
                              void* d_out, int out_size)
{
    const float* x     = (const float*)d_in[0];
    const float* gamma = (const float*)d_in[1];
    const float* beta  = (const float*)d_in[2];
    const float* Wa    = (const float*)d_in[3];
    const float* Wb    = (const float*)d_in[4];
    const float* Wo    = (const float*)d_in[5];
    const float* bo    = (const float*)d_in[6];
    float* z = (float*)d_out;

    kA<<<L, 256>>>(x, gamma, beta, Wa, Wb);
    kB<<<dim3(48, 8), 256>>>(Wo);
    kC<<<dim3(L, 3), 256>>>(bo, z);
}